// round 11
// baseline (speedup 1.0000x reference)
#include <cuda_runtime.h>
#include <cuda_bf16.h>

#define BB 4
#define SS_DIM 1024
#define XX 1024
#define CC 8
#define DD 2
#define WIDTH 16
#define DEPTH 4
#define TPB 256
#define NCHUNK (SS_DIM / 32)
#define WB_PAD 10   // padded kpair stride for LDS.64 conflict mitigation

__device__ __forceinline__ float fast_tanh(float x) {
    float y; asm("tanh.approx.f32 %0, %1;" : "=f"(y) : "f"(x)); return y;
}
__device__ __forceinline__ unsigned pack_bf16x2(float lo, float hi) {
    unsigned d; asm("cvt.rn.bf16x2.f32 %0, %1, %2;" : "=r"(d) : "f"(hi), "f"(lo)); return d;
}
__device__ __forceinline__ float bf16lo_as_f32(unsigned p) { return __uint_as_float(p << 16); }
__device__ __forceinline__ float bf16hi_as_f32(unsigned p) { return __uint_as_float(p & 0xffff0000u); }
__device__ __forceinline__ void split_pack(float e0, float e1, unsigned& hi, unsigned& lo) {
    hi = pack_bf16x2(e0, e1);
    lo = pack_bf16x2(e0 - bf16lo_as_f32(hi), e1 - bf16hi_as_f32(hi));
}
__device__ __forceinline__ void mma_bf16_init(float* d, const unsigned* a,
                                              unsigned b0, unsigned b1,
                                              float c0, float c1) {
    asm("mma.sync.aligned.m16n8k16.row.col.f32.bf16.bf16.f32 "
        "{%0,%1,%2,%3}, {%4,%5,%6,%7}, {%8,%9}, {%10,%11,%10,%11};"
        : "=f"(d[0]), "=f"(d[1]), "=f"(d[2]), "=f"(d[3])
        : "r"(a[0]), "r"(a[1]), "r"(a[2]), "r"(a[3]), "r"(b0), "r"(b1),
          "f"(c0), "f"(c1));
}
__device__ __forceinline__ void mma_bf16(float* c, const unsigned* a,
                                         unsigned b0, unsigned b1) {
    asm("mma.sync.aligned.m16n8k16.row.col.f32.bf16.bf16.f32 "
        "{%0,%1,%2,%3}, {%4,%5,%6,%7}, {%8,%9}, {%0,%1,%2,%3};"
        : "+f"(c[0]), "+f"(c[1]), "+f"(c[2]), "+f"(c[3])
        : "r"(a[0]), "r"(a[1]), "r"(a[2]), "r"(a[3]), "r"(b0), "r"(b1));
}

__global__ __launch_bounds__(TPB, 4)
void ccl_kernel(const float* __restrict__ yu,
                const float* __restrict__ xin,
                const float* __restrict__ gWin,
                const float* __restrict__ gbin,
                const float* __restrict__ gWhid,
                const float* __restrict__ gbhid,
                const float* __restrict__ gWout,
                const float* __restrict__ gbout,
                float* __restrict__ out) {
    __shared__ float  s_u[SS_DIM][CC];            // 32KB
    __shared__ float2 s_y[SS_DIM];                // 8KB
    __shared__ uint2  s_WB[DEPTH][WIDTH][WB_PAD]; // 5KB pre-split (hi,lo) bf16x2 pairs
    __shared__ float  s_bias[DEPTH][WIDTH];
    __shared__ float  s_win[WIDTH];
    __shared__ float  s_bin[WIDTH];
    __shared__ float  s_wout[WIDTH];

    const int t    = threadIdx.x;
    const int warp = t >> 5;
    const int lane = t & 31;
    const int g    = lane >> 2;
    const int q    = lane & 3;
    const int b    = blockIdx.y;
    const int xi   = blockIdx.x * 8 + warp;

    // ---- stage yu[b], weight table, small vectors ----
    for (int i = t; i < SS_DIM; i += TPB) {
        const float2* row = (const float2*)(yu + ((size_t)b * SS_DIM + i) * (CC + DD));
        const float2 a0 = row[0], a1 = row[1], a2 = row[2], a3 = row[3], yv = row[4];
        float2* ur = (float2*)&s_u[i][0];
        ur[0] = a0; ur[1] = a1; ur[2] = a2; ur[3] = a3;
        s_y[i] = yv;
    }
    for (int idx = t; idx < DEPTH * WIDTH * 8; idx += TPB) {
        const int l  = idx >> 7;
        const int r7 = idx & 127;
        const int n  = r7 >> 3;
        const int kp = r7 & 7;
        const float w0 = gWhid[((l * WIDTH) + 2 * kp) * WIDTH + n];
        const float w1 = gWhid[((l * WIDTH) + 2 * kp + 1) * WIDTH + n];
        unsigned hi, lo;
        split_pack(w0, w1, hi, lo);
        s_WB[l][n][kp] = make_uint2(hi, lo);
    }
    if (t < DEPTH * WIDTH) ((float*)s_bias)[t] = gbhid[t];
    if (t < WIDTH) {
        s_win[t]  = gWin[t];
        s_bin[t]  = gbin[t];
        s_wout[t] = gWout[t];
    }
    __syncthreads();

    const float bout = gbout[0];
    const float2 xv = *(const float2*)(xin + ((size_t)b * XX + xi) * DD);

    float acc0 = 0.0f, acc1 = 0.0f;

#pragma unroll 1
    for (int ch = 0; ch < NCHUNK; ++ch) {
        const int s0 = ch * 32;

        const float2 yv = s_y[s0 + lane];
        const float dx0 = xv.x - yv.x;
        const float dx1 = xv.y - yv.y;
        const float r = fmaf(dx1, dx1, dx0 * dx0);
        const float r0 = __shfl_sync(0xffffffffu, r, g);
        const float r1 = __shfl_sync(0xffffffffu, r, g + 8);
        const float r2 = __shfl_sync(0xffffffffu, r, g + 16);
        const float r3 = __shfl_sync(0xffffffffu, r, g + 24);

        const float2 wA  = ((const float2*)s_win)[q];
        const float2 wB  = ((const float2*)(s_win + 8))[q];
        const float2 biA = ((const float2*)s_bin)[q];
        const float2 biB = ((const float2*)(s_bin + 8))[q];

        float hD[2][2][4];
#pragma unroll
        for (int nt = 0; nt < 2; ++nt) {
            const float2 wv = nt ? wB : wA;
            const float2 bv = nt ? biB : biA;
            hD[0][nt][0] = fmaf(r0, wv.x, bv.x);
            hD[0][nt][1] = fmaf(r0, wv.y, bv.y);
            hD[0][nt][2] = fmaf(r1, wv.x, bv.x);
            hD[0][nt][3] = fmaf(r1, wv.y, bv.y);
            hD[1][nt][0] = fmaf(r2, wv.x, bv.x);
            hD[1][nt][1] = fmaf(r2, wv.y, bv.y);
            hD[1][nt][2] = fmaf(r3, wv.x, bv.x);
            hD[1][nt][3] = fmaf(r3, wv.y, bv.y);
        }

#pragma unroll
        for (int l = 0; l < DEPTH; ++l) {
            const uint2 w00 = s_WB[l][g][q];         // nt0, rows 2q..2q+1
            const uint2 w01 = s_WB[l][g][q + 4];     // nt0, rows 2q+8..2q+9
            const uint2 w10 = s_WB[l][g + 8][q];     // nt1
            const uint2 w11 = s_WB[l][g + 8][q + 4]; // nt1
            const float2 bhA = ((const float2*)&s_bias[l][0])[q];
            const float2 bhB = ((const float2*)&s_bias[l][8])[q];
#pragma unroll
            for (int mt = 0; mt < 2; ++mt) {
                unsigned ahi[4], alo[4];
                split_pack(hD[mt][0][0], hD[mt][0][1], ahi[0], alo[0]);
                split_pack(hD[mt][0][2], hD[mt][0][3], ahi[1], alo[1]);
                split_pack(hD[mt][1][0], hD[mt][1][1], ahi[2], alo[2]);
                split_pack(hD[mt][1][2], hD[mt][1][3], ahi[3], alo[3]);
#pragma unroll
                for (int nt = 0; nt < 2; ++nt) {
                    const unsigned bh0 = nt ? w10.x : w00.x;
                    const unsigned bh1 = nt ? w11.x : w01.x;
                    const unsigned bl0 = nt ? w10.y : w00.y;
                    const unsigned bl1 = nt ? w11.y : w01.y;
                    float z[4];
                    mma_bf16_init(z, ahi, bh0, bh1,
                                  nt ? bhB.x : bhA.x, nt ? bhB.y : bhA.y);
                    mma_bf16(z, ahi, bl0, bl1);
                    mma_bf16(z, alo, bh0, bh1);
#pragma unroll
                    for (int c = 0; c < 4; ++c)
                        hD[mt][nt][c] += fast_tanh(z[c]);
                }
            }
        }

        const float2 woA = ((const float2*)s_wout)[q];
        const float2 woB = ((const float2*)(s_wout + 8))[q];
        float k[4];
#pragma unroll
        for (int mt = 0; mt < 2; ++mt) {
            float pg  = fmaf(hD[mt][0][0], woA.x,
                        fmaf(hD[mt][0][1], woA.y,
                        fmaf(hD[mt][1][0], woB.x, hD[mt][1][1] * woB.y)));
            float pg8 = fmaf(hD[mt][0][2], woA.x,
                        fmaf(hD[mt][0][3], woA.y,
                        fmaf(hD[mt][1][2], woB.x, hD[mt][1][3] * woB.y)));
            pg  += __shfl_xor_sync(0xffffffffu, pg, 1);
            pg  += __shfl_xor_sync(0xffffffffu, pg, 2);
            pg8 += __shfl_xor_sync(0xffffffffu, pg8, 1);
            pg8 += __shfl_xor_sync(0xffffffffu, pg8, 2);
            k[2 * mt]     = pg + bout;
            k[2 * mt + 1] = pg8 + bout;
        }

        const int srow[4] = {s0 + g, s0 + g + 8, s0 + 16 + g, s0 + 24 + g};
#pragma unroll
        for (int i = 0; i < 4; ++i) {
            const float2 uv = *(const float2*)&s_u[srow[i]][2 * q];
            acc0 = fmaf(k[i], uv.x, acc0);
            acc1 = fmaf(k[i], uv.y, acc1);
        }
    }

#pragma unroll
    for (int off = 4; off < 32; off <<= 1) {
        acc0 += __shfl_xor_sync(0xffffffffu, acc0, off);
        acc1 += __shfl_xor_sync(0xffffffffu, acc1, off);
    }
    if (lane < 4) {
        const float invS = 1.0f / (float)SS_DIM;
        float2 v = make_float2(acc0 * invS, acc1 * invS);
        *(float2*)(out + ((size_t)b * XX + xi) * CC + 2 * lane) = v;
    }
}

extern "C" void kernel_launch(void* const* d_in, const int* in_sizes, int n_in,
                              void* d_out, int out_size) {
    const float* yu    = (const float*)d_in[0]; // (4,1024,10)
    const float* x     = (const float*)d_in[1]; // (4,1024,2)
    const float* W_in  = (const float*)d_in[2]; // (1,16)
    const float* b_in  = (const float*)d_in[3]; // (16,)
    const float* W_hid = (const float*)d_in[4]; // (4,16,16)
    const float* b_hid = (const float*)d_in[5]; // (4,16)
    const float* W_out = (const float*)d_in[6]; // (16,1)
    const float* b_out = (const float*)d_in[7]; // (1,)

    (void)in_sizes; (void)n_in; (void)out_size;

    dim3 grid(XX / 8, BB, 1);   // 512 blocks, 8 warps each -> single resident wave
    ccl_kernel<<<grid, TPB, 0, 0>>>(yu, x, W_in, b_in, W_hid, b_hid, W_out, b_out,
                                    (float*)d_out);
}

// round 12
// speedup vs baseline: 1.1093x; 1.1093x over previous
#include <cuda_runtime.h>
#include <cuda_bf16.h>

#define BB 4
#define SS_DIM 1024
#define XX 1024
#define CC 8
#define DD 2
#define WIDTH 16
#define DEPTH 4
#define TPB 128
#define NCHUNK (SS_DIM / 32)

__device__ __forceinline__ float fast_tanh(float x) {
    float y; asm("tanh.approx.f32 %0, %1;" : "=f"(y) : "f"(x)); return y;
}
__device__ __forceinline__ unsigned pack_bf16x2(float lo, float hi) {
    unsigned d; asm("cvt.rn.bf16x2.f32 %0, %1, %2;" : "=r"(d) : "f"(hi), "f"(lo)); return d;
}
__device__ __forceinline__ float bf16lo_as_f32(unsigned p) { return __uint_as_float(p << 16); }
__device__ __forceinline__ float bf16hi_as_f32(unsigned p) { return __uint_as_float(p & 0xffff0000u); }
__device__ __forceinline__ void split_pack(float e0, float e1, unsigned& hi, unsigned& lo) {
    hi = pack_bf16x2(e0, e1);
    lo = pack_bf16x2(e0 - bf16lo_as_f32(hi), e1 - bf16hi_as_f32(hi));
}
__device__ __forceinline__ void mma_bf16_init(float* d, const unsigned* a,
                                              unsigned b0, unsigned b1,
                                              float c0, float c1) {
    asm("mma.sync.aligned.m16n8k16.row.col.f32.bf16.bf16.f32 "
        "{%0,%1,%2,%3}, {%4,%5,%6,%7}, {%8,%9}, {%10,%11,%10,%11};"
        : "=f"(d[0]), "=f"(d[1]), "=f"(d[2]), "=f"(d[3])
        : "r"(a[0]), "r"(a[1]), "r"(a[2]), "r"(a[3]), "r"(b0), "r"(b1),
          "f"(c0), "f"(c1));
}
__device__ __forceinline__ void mma_bf16(float* c, const unsigned* a,
                                         unsigned b0, unsigned b1) {
    asm("mma.sync.aligned.m16n8k16.row.col.f32.bf16.bf16.f32 "
        "{%0,%1,%2,%3}, {%4,%5,%6,%7}, {%8,%9}, {%0,%1,%2,%3};"
        : "+f"(c[0]), "+f"(c[1]), "+f"(c[2]), "+f"(c[3])
        : "r"(a[0]), "r"(a[1]), "r"(a[2]), "r"(a[3]), "r"(b0), "r"(b1));
}

__global__ __launch_bounds__(TPB, 4)
void ccl_kernel(const float* __restrict__ yu,
                const float* __restrict__ xin,
                const float* __restrict__ gWin,
                const float* __restrict__ gbin,
                const float* __restrict__ gWhid,
                const float* __restrict__ gbhid,
                const float* __restrict__ gWout,
                const float* __restrict__ gbout,
                float* __restrict__ out) {
    __shared__ float  s_u[SS_DIM][CC];      // 32KB
    __shared__ float2 s_y[SS_DIM];          // 8KB
    __shared__ float  s_bias[DEPTH][WIDTH];
    __shared__ float  s_win[WIDTH];
    __shared__ float  s_bin[WIDTH];
    __shared__ float  s_wout[WIDTH];

    const int t    = threadIdx.x;
    const int warp = t >> 5;
    const int lane = t & 31;
    const int g    = lane >> 2;
    const int q    = lane & 3;
    const int b    = blockIdx.y;
    const int xiA  = blockIdx.x * 8 + 2 * warp;   // two xi per warp
    const int xiB  = xiA + 1;

    // ---- stage yu[b] + small weights ----
    for (int i = t; i < SS_DIM; i += TPB) {
        const float2* row = (const float2*)(yu + ((size_t)b * SS_DIM + i) * (CC + DD));
        const float2 a0 = row[0], a1 = row[1], a2 = row[2], a3 = row[3], yv = row[4];
        float2* ur = (float2*)&s_u[i][0];
        ur[0] = a0; ur[1] = a1; ur[2] = a2; ur[3] = a3;
        s_y[i] = yv;
    }
    if (t < DEPTH * WIDTH) ((float*)s_bias)[t] = gbhid[t];
    if (t < WIDTH) {
        s_win[t]  = gWin[t];
        s_bin[t]  = gbin[t];
        s_wout[t] = gWout[t];
    }
    __syncthreads();

    const float bout = gbout[0];

    // ---- register-resident B fragments (shared by both xi streams) ----
    unsigned Bhi[DEPTH][2][2], Blo[DEPTH][2][2];
#pragma unroll
    for (int l = 0; l < DEPTH; ++l) {
        const float* Wl = gWhid + l * WIDTH * WIDTH;
#pragma unroll
        for (int nt = 0; nt < 2; ++nt) {
            const int n = g + 8 * nt;
            const float w00 = Wl[(2 * q) * WIDTH + n];
            const float w01 = Wl[(2 * q + 1) * WIDTH + n];
            const float w10 = Wl[(2 * q + 8) * WIDTH + n];
            const float w11 = Wl[(2 * q + 9) * WIDTH + n];
            split_pack(w00, w01, Bhi[l][nt][0], Blo[l][nt][0]);
            split_pack(w10, w11, Bhi[l][nt][1], Blo[l][nt][1]);
        }
    }

    const float2 xvA = *(const float2*)(xin + ((size_t)b * XX + xiA) * DD);
    const float2 xvB = *(const float2*)(xin + ((size_t)b * XX + xiB) * DD);

    float accA0 = 0.0f, accA1 = 0.0f, accB0 = 0.0f, accB1 = 0.0f;

#pragma unroll 1
    for (int ch = 0; ch < NCHUNK; ++ch) {
        const int s0 = ch * 32;

        const float2 yv = s_y[s0 + lane];
        float dx = xvA.x - yv.x, dy = xvA.y - yv.y;
        const float rA = fmaf(dy, dy, dx * dx);
        dx = xvB.x - yv.x; dy = xvB.y - yv.y;
        const float rB = fmaf(dy, dy, dx * dx);

        float rg[2][4];
        rg[0][0] = __shfl_sync(0xffffffffu, rA, g);
        rg[0][1] = __shfl_sync(0xffffffffu, rA, g + 8);
        rg[0][2] = __shfl_sync(0xffffffffu, rA, g + 16);
        rg[0][3] = __shfl_sync(0xffffffffu, rA, g + 24);
        rg[1][0] = __shfl_sync(0xffffffffu, rB, g);
        rg[1][1] = __shfl_sync(0xffffffffu, rB, g + 8);
        rg[1][2] = __shfl_sync(0xffffffffu, rB, g + 16);
        rg[1][3] = __shfl_sync(0xffffffffu, rB, g + 24);

        const float2 wA  = ((const float2*)s_win)[q];
        const float2 wB  = ((const float2*)(s_win + 8))[q];
        const float2 biA = ((const float2*)s_bin)[q];
        const float2 biB = ((const float2*)(s_bin + 8))[q];

        float hD[2][2][2][4];   // [px][mt][nt][c]
#pragma unroll
        for (int px = 0; px < 2; ++px)
#pragma unroll
            for (int nt = 0; nt < 2; ++nt) {
                const float2 wv = nt ? wB : wA;
                const float2 bv = nt ? biB : biA;
                hD[px][0][nt][0] = fmaf(rg[px][0], wv.x, bv.x);
                hD[px][0][nt][1] = fmaf(rg[px][0], wv.y, bv.y);
                hD[px][0][nt][2] = fmaf(rg[px][1], wv.x, bv.x);
                hD[px][0][nt][3] = fmaf(rg[px][1], wv.y, bv.y);
                hD[px][1][nt][0] = fmaf(rg[px][2], wv.x, bv.x);
                hD[px][1][nt][1] = fmaf(rg[px][2], wv.y, bv.y);
                hD[px][1][nt][2] = fmaf(rg[px][3], wv.x, bv.x);
                hD[px][1][nt][3] = fmaf(rg[px][3], wv.y, bv.y);
            }

#pragma unroll
        for (int l = 0; l < DEPTH; ++l) {
            const float2 bhA = ((const float2*)&s_bias[l][0])[q];
            const float2 bhB = ((const float2*)&s_bias[l][8])[q];
#pragma unroll
            for (int px = 0; px < 2; ++px) {
#pragma unroll
                for (int mt = 0; mt < 2; ++mt) {
                    unsigned ahi[4], alo[4];
                    split_pack(hD[px][mt][0][0], hD[px][mt][0][1], ahi[0], alo[0]);
                    split_pack(hD[px][mt][0][2], hD[px][mt][0][3], ahi[1], alo[1]);
                    split_pack(hD[px][mt][1][0], hD[px][mt][1][1], ahi[2], alo[2]);
                    split_pack(hD[px][mt][1][2], hD[px][mt][1][3], ahi[3], alo[3]);
#pragma unroll
                    for (int nt = 0; nt < 2; ++nt) {
                        float z[4];
                        mma_bf16_init(z, ahi, Bhi[l][nt][0], Bhi[l][nt][1],
                                      nt ? bhB.x : bhA.x, nt ? bhB.y : bhA.y);
                        mma_bf16(z, ahi, Blo[l][nt][0], Blo[l][nt][1]);
                        mma_bf16(z, alo, Bhi[l][nt][0], Bhi[l][nt][1]);
#pragma unroll
                        for (int c = 0; c < 4; ++c)
                            hD[px][mt][nt][c] += fast_tanh(z[c]);
                    }
                }
            }
        }

        const float2 woA = ((const float2*)s_wout)[q];
        const float2 woB = ((const float2*)(s_wout + 8))[q];
        float k[2][4];
#pragma unroll
        for (int px = 0; px < 2; ++px)
#pragma unroll
            for (int mt = 0; mt < 2; ++mt) {
                float pg  = fmaf(hD[px][mt][0][0], woA.x,
                            fmaf(hD[px][mt][0][1], woA.y,
                            fmaf(hD[px][mt][1][0], woB.x, hD[px][mt][1][1] * woB.y)));
                float pg8 = fmaf(hD[px][mt][0][2], woA.x,
                            fmaf(hD[px][mt][0][3], woA.y,
                            fmaf(hD[px][mt][1][2], woB.x, hD[px][mt][1][3] * woB.y)));
                pg  += __shfl_xor_sync(0xffffffffu, pg, 1);
                pg  += __shfl_xor_sync(0xffffffffu, pg, 2);
                pg8 += __shfl_xor_sync(0xffffffffu, pg8, 1);
                pg8 += __shfl_xor_sync(0xffffffffu, pg8, 2);
                k[px][2 * mt]     = pg + bout;
                k[px][2 * mt + 1] = pg8 + bout;
            }

        const int srow[4] = {s0 + g, s0 + g + 8, s0 + 16 + g, s0 + 24 + g};
#pragma unroll
        for (int i = 0; i < 4; ++i) {
            const float2 uv = *(const float2*)&s_u[srow[i]][2 * q];   // shared by both xi
            accA0 = fmaf(k[0][i], uv.x, accA0);
            accA1 = fmaf(k[0][i], uv.y, accA1);
            accB0 = fmaf(k[1][i], uv.x, accB0);
            accB1 = fmaf(k[1][i], uv.y, accB1);
        }
    }

#pragma unroll
    for (int off = 4; off < 32; off <<= 1) {
        accA0 += __shfl_xor_sync(0xffffffffu, accA0, off);
        accA1 += __shfl_xor_sync(0xffffffffu, accA1, off);
        accB0 += __shfl_xor_sync(0xffffffffu, accB0, off);
        accB1 += __shfl_xor_sync(0xffffffffu, accB1, off);
    }
    if (lane < 4) {
        const float invS = 1.0f / (float)SS_DIM;
        *(float2*)(out + ((size_t)b * XX + xiA) * CC + 2 * lane) =
            make_float2(accA0 * invS, accA1 * invS);
        *(float2*)(out + ((size_t)b * XX + xiB) * CC + 2 * lane) =
            make_float2(accB0 * invS, accB1 * invS);
    }
}

extern "C" void kernel_launch(void* const* d_in, const int* in_sizes, int n_in,
                              void* d_out, int out_size) {
    const float* yu    = (const float*)d_in[0]; // (4,1024,10)
    const float* x     = (const float*)d_in[1]; // (4,1024,2)
    const float* W_in  = (const float*)d_in[2]; // (1,16)
    const float* b_in  = (const float*)d_in[3]; // (16,)
    const float* W_hid = (const float*)d_in[4]; // (4,16,16)
    const float* b_hid = (const float*)d_in[5]; // (4,16)
    const float* W_out = (const float*)d_in[6]; // (16,1)
    const float* b_out = (const float*)d_in[7]; // (1,)

    (void)in_sizes; (void)n_in; (void)out_size;

    dim3 grid(XX / 8, BB, 1);   // 512 blocks x 4 warps x 2 xi = 4096 xi-streams, single wave
    ccl_kernel<<<grid, TPB, 0, 0>>>(yu, x, W_in, b_in, W_hid, b_hid, W_out, b_out,
                                    (float*)d_out);
}

// round 13
// speedup vs baseline: 1.6115x; 1.4526x over previous
#include <cuda_runtime.h>
#include <cuda_fp16.h>

#define BB 4
#define SS_DIM 1024
#define XX 1024
#define CC 8
#define DD 2
#define WIDTH 16
#define DEPTH 4
#define TPB 128
#define NCHUNK (SS_DIM / 32)

__device__ __forceinline__ float fast_tanh(float x) {
    float y; asm("tanh.approx.f32 %0, %1;" : "=f"(y) : "f"(x)); return y;
}
// pack two f32 -> f16x2; e0 lands in LOWER half (element k even), e1 in upper
__device__ __forceinline__ unsigned pack_f16x2(float e0, float e1) {
    unsigned d; asm("cvt.rn.f16x2.f32 %0, %1, %2;" : "=r"(d) : "f"(e1), "f"(e0)); return d;
}
// 2-term f16 split for weights (prologue only)
__device__ __forceinline__ void split_pack_f16(float e0, float e1, unsigned& hi, unsigned& lo) {
    hi = pack_f16x2(e0, e1);
    const __half2 h2 = *reinterpret_cast<const __half2*>(&hi);
    lo = pack_f16x2(e0 - __half2float(__low2half(h2)),
                    e1 - __half2float(__high2half(h2)));
}
__device__ __forceinline__ void mma_f16_init(float* d, const unsigned* a,
                                             unsigned b0, unsigned b1,
                                             float c0, float c1) {
    asm("mma.sync.aligned.m16n8k16.row.col.f32.f16.f16.f32 "
        "{%0,%1,%2,%3}, {%4,%5,%6,%7}, {%8,%9}, {%10,%11,%10,%11};"
        : "=f"(d[0]), "=f"(d[1]), "=f"(d[2]), "=f"(d[3])
        : "r"(a[0]), "r"(a[1]), "r"(a[2]), "r"(a[3]), "r"(b0), "r"(b1),
          "f"(c0), "f"(c1));
}
__device__ __forceinline__ void mma_f16(float* c, const unsigned* a,
                                        unsigned b0, unsigned b1) {
    asm("mma.sync.aligned.m16n8k16.row.col.f32.f16.f16.f32 "
        "{%0,%1,%2,%3}, {%4,%5,%6,%7}, {%8,%9}, {%0,%1,%2,%3};"
        : "+f"(c[0]), "+f"(c[1]), "+f"(c[2]), "+f"(c[3])
        : "r"(a[0]), "r"(a[1]), "r"(a[2]), "r"(a[3]), "r"(b0), "r"(b1));
}

__global__ __launch_bounds__(TPB, 5)
void ccl_kernel(const float* __restrict__ yu,
                const float* __restrict__ xin,
                const float* __restrict__ gWin,
                const float* __restrict__ gbin,
                const float* __restrict__ gWhid,
                const float* __restrict__ gbhid,
                const float* __restrict__ gWout,
                const float* __restrict__ gbout,
                float* __restrict__ out) {
    __shared__ float  s_u[SS_DIM][CC];      // 32KB
    __shared__ float2 s_y[SS_DIM];          // 8KB
    __shared__ float  s_bias[DEPTH][WIDTH];
    __shared__ float  s_win[WIDTH];
    __shared__ float  s_bin[WIDTH];
    __shared__ float  s_wout[WIDTH];

    const int t    = threadIdx.x;
    const int warp = t >> 5;
    const int lane = t & 31;
    const int g    = lane >> 2;
    const int q    = lane & 3;
    const int b    = blockIdx.y;
    const int xi   = blockIdx.x * 4 + warp;

    // ---- stage yu[b] + small weights ----
    for (int i = t; i < SS_DIM; i += TPB) {
        const float2* row = (const float2*)(yu + ((size_t)b * SS_DIM + i) * (CC + DD));
        const float2 a0 = row[0], a1 = row[1], a2 = row[2], a3 = row[3], yv = row[4];
        float2* ur = (float2*)&s_u[i][0];
        ur[0] = a0; ur[1] = a1; ur[2] = a2; ur[3] = a3;
        s_y[i] = yv;
    }
    if (t < DEPTH * WIDTH) ((float*)s_bias)[t] = gbhid[t];
    if (t < WIDTH) {
        s_win[t]  = gWin[t];
        s_bin[t]  = gbin[t];
        s_wout[t] = gWout[t];
    }
    __syncthreads();

    const float bout = gbout[0];

    // ---- register-resident B fragments, 2-term fp16 split (exact weights) ----
    unsigned Bhi[DEPTH][2][2], Blo[DEPTH][2][2];
#pragma unroll
    for (int l = 0; l < DEPTH; ++l) {
        const float* Wl = gWhid + l * WIDTH * WIDTH;
#pragma unroll
        for (int nt = 0; nt < 2; ++nt) {
            const int n = g + 8 * nt;
            const float w00 = Wl[(2 * q) * WIDTH + n];
            const float w01 = Wl[(2 * q + 1) * WIDTH + n];
            const float w10 = Wl[(2 * q + 8) * WIDTH + n];
            const float w11 = Wl[(2 * q + 9) * WIDTH + n];
            split_pack_f16(w00, w01, Bhi[l][nt][0], Blo[l][nt][0]);
            split_pack_f16(w10, w11, Bhi[l][nt][1], Blo[l][nt][1]);
        }
    }

    const float2 xv = *(const float2*)(xin + ((size_t)b * XX + xi) * DD);

    float acc0 = 0.0f, acc1 = 0.0f;

#pragma unroll 1
    for (int ch = 0; ch < NCHUNK; ++ch) {
        const int s0 = ch * 32;

        const float2 yv = s_y[s0 + lane];
        const float dx0 = xv.x - yv.x;
        const float dx1 = xv.y - yv.y;
        const float r = fmaf(dx1, dx1, dx0 * dx0);
        const float r0 = __shfl_sync(0xffffffffu, r, g);
        const float r1 = __shfl_sync(0xffffffffu, r, g + 8);
        const float r2 = __shfl_sync(0xffffffffu, r, g + 16);
        const float r3 = __shfl_sync(0xffffffffu, r, g + 24);

        const float2 wA  = ((const float2*)s_win)[q];
        const float2 wB  = ((const float2*)(s_win + 8))[q];
        const float2 biA = ((const float2*)s_bin)[q];
        const float2 biB = ((const float2*)(s_bin + 8))[q];

        float hD[2][2][4];
#pragma unroll
        for (int nt = 0; nt < 2; ++nt) {
            const float2 wv = nt ? wB : wA;
            const float2 bv = nt ? biB : biA;
            hD[0][nt][0] = fmaf(r0, wv.x, bv.x);
            hD[0][nt][1] = fmaf(r0, wv.y, bv.y);
            hD[0][nt][2] = fmaf(r1, wv.x, bv.x);
            hD[0][nt][3] = fmaf(r1, wv.y, bv.y);
            hD[1][nt][0] = fmaf(r2, wv.x, bv.x);
            hD[1][nt][1] = fmaf(r2, wv.y, bv.y);
            hD[1][nt][2] = fmaf(r3, wv.x, bv.x);
            hD[1][nt][3] = fmaf(r3, wv.y, bv.y);
        }

#pragma unroll
        for (int l = 0; l < DEPTH; ++l) {
            const float2 bhA = ((const float2*)&s_bias[l][0])[q];
            const float2 bhB = ((const float2*)&s_bias[l][8])[q];
#pragma unroll
            for (int mt = 0; mt < 2; ++mt) {
                // single-fp16 A fragment: 4 CVTs, no residual
                unsigned a[4];
                a[0] = pack_f16x2(hD[mt][0][0], hD[mt][0][1]);
                a[1] = pack_f16x2(hD[mt][0][2], hD[mt][0][3]);
                a[2] = pack_f16x2(hD[mt][1][0], hD[mt][1][1]);
                a[3] = pack_f16x2(hD[mt][1][2], hD[mt][1][3]);
#pragma unroll
                for (int nt = 0; nt < 2; ++nt) {
                    float z[4];
                    mma_f16_init(z, a, Bhi[l][nt][0], Bhi[l][nt][1],
                                 nt ? bhB.x : bhA.x, nt ? bhB.y : bhA.y);
                    mma_f16(z, a, Blo[l][nt][0], Blo[l][nt][1]);
#pragma unroll
                    for (int c = 0; c < 4; ++c)
                        hD[mt][nt][c] += fast_tanh(z[c]);
                }
            }
        }

        const float2 woA = ((const float2*)s_wout)[q];
        const float2 woB = ((const float2*)(s_wout + 8))[q];
        float k[4];
#pragma unroll
        for (int mt = 0; mt < 2; ++mt) {
            float pg  = fmaf(hD[mt][0][0], woA.x,
                        fmaf(hD[mt][0][1], woA.y,
                        fmaf(hD[mt][1][0], woB.x, hD[mt][1][1] * woB.y)));
            float pg8 = fmaf(hD[mt][0][2], woA.x,
                        fmaf(hD[mt][0][3], woA.y,
                        fmaf(hD[mt][1][2], woB.x, hD[mt][1][3] * woB.y)));
            pg  += __shfl_xor_sync(0xffffffffu, pg, 1);
            pg  += __shfl_xor_sync(0xffffffffu, pg, 2);
            pg8 += __shfl_xor_sync(0xffffffffu, pg8, 1);
            pg8 += __shfl_xor_sync(0xffffffffu, pg8, 2);
            k[2 * mt]     = pg + bout;
            k[2 * mt + 1] = pg8 + bout;
        }

        const int srow[4] = {s0 + g, s0 + g + 8, s0 + 16 + g, s0 + 24 + g};
#pragma unroll
        for (int i = 0; i < 4; ++i) {
            const float2 uv = *(const float2*)&s_u[srow[i]][2 * q];
            acc0 = fmaf(k[i], uv.x, acc0);
            acc1 = fmaf(k[i], uv.y, acc1);
        }
    }

#pragma unroll
    for (int off = 4; off < 32; off <<= 1) {
        acc0 += __shfl_xor_sync(0xffffffffu, acc0, off);
        acc1 += __shfl_xor_sync(0xffffffffu, acc1, off);
    }
    if (lane < 4) {
        const float invS = 1.0f / (float)SS_DIM;
        float2 v = make_float2(acc0 * invS, acc1 * invS);
        *(float2*)(out + ((size_t)b * XX + xi) * CC + 2 * lane) = v;
    }
}

extern "C" void kernel_launch(void* const* d_in, const int* in_sizes, int n_in,
                              void* d_out, int out_size) {
    const float* yu    = (const float*)d_in[0]; // (4,1024,10)
    const float* x     = (const float*)d_in[1]; // (4,1024,2)
    const float* W_in  = (const float*)d_in[2]; // (1,16)
    const float* b_in  = (const float*)d_in[3]; // (16,)
    const float* W_hid = (const float*)d_in[4]; // (4,16,16)
    const float* b_hid = (const float*)d_in[5]; // (4,16)
    const float* W_out = (const float*)d_in[6]; // (16,1)
    const float* b_out = (const float*)d_in[7]; // (1,)

    (void)in_sizes; (void)n_in; (void)out_size;

    dim3 grid(XX / 4, BB, 1);   // identical launch shape to the 103us best
    ccl_kernel<<<grid, TPB, 0, 0>>>(yu, x, W_in, b_in, W_hid, b_hid, W_out, b_out,
                                    (float*)d_out);
}

// round 14
// speedup vs baseline: 1.6205x; 1.0056x over previous
#include <cuda_runtime.h>
#include <cuda_fp16.h>

#define BB 4
#define SS_DIM 1024
#define XX 1024
#define CC 8
#define DD 2
#define WIDTH 16
#define DEPTH 4
#define TPB 128
#define SHALF 512
#define NCHUNK (SHALF / 32)

__device__ __forceinline__ float fast_tanh(float x) {
    float y; asm("tanh.approx.f32 %0, %1;" : "=f"(y) : "f"(x)); return y;
}
// pack two f32 -> f16x2; e0 lands in LOWER half
__device__ __forceinline__ unsigned pack_f16x2(float e0, float e1) {
    unsigned d; asm("cvt.rn.f16x2.f32 %0, %1, %2;" : "=r"(d) : "f"(e1), "f"(e0)); return d;
}
// 2-term f16 split for weights (prologue only)
__device__ __forceinline__ void split_pack_f16(float e0, float e1, unsigned& hi, unsigned& lo) {
    hi = pack_f16x2(e0, e1);
    const __half2 h2 = *reinterpret_cast<const __half2*>(&hi);
    lo = pack_f16x2(e0 - __half2float(__low2half(h2)),
                    e1 - __half2float(__high2half(h2)));
}
__device__ __forceinline__ void mma_f16_init(float* d, const unsigned* a,
                                             unsigned b0, unsigned b1,
                                             float c0, float c1) {
    asm("mma.sync.aligned.m16n8k16.row.col.f32.f16.f16.f32 "
        "{%0,%1,%2,%3}, {%4,%5,%6,%7}, {%8,%9}, {%10,%11,%10,%11};"
        : "=f"(d[0]), "=f"(d[1]), "=f"(d[2]), "=f"(d[3])
        : "r"(a[0]), "r"(a[1]), "r"(a[2]), "r"(a[3]), "r"(b0), "r"(b1),
          "f"(c0), "f"(c1));
}
__device__ __forceinline__ void mma_f16(float* c, const unsigned* a,
                                        unsigned b0, unsigned b1) {
    asm("mma.sync.aligned.m16n8k16.row.col.f32.f16.f16.f32 "
        "{%0,%1,%2,%3}, {%4,%5,%6,%7}, {%8,%9}, {%0,%1,%2,%3};"
        : "+f"(c[0]), "+f"(c[1]), "+f"(c[2]), "+f"(c[3])
        : "r"(a[0]), "r"(a[1]), "r"(a[2]), "r"(a[3]), "r"(b0), "r"(b1));
}

__global__ __launch_bounds__(TPB, 5)
void ccl_kernel(const float* __restrict__ yu,
                const float* __restrict__ xin,
                const float* __restrict__ gWin,
                const float* __restrict__ gbin,
                const float* __restrict__ gWhid,
                const float* __restrict__ gbhid,
                const float* __restrict__ gWout,
                const float* __restrict__ gbout,
                float* __restrict__ out) {
    __shared__ float  s_u[SHALF][CC];      // 16KB (this block's s-half)
    __shared__ float2 s_y[SHALF];          // 4KB
    __shared__ float  s_bias[DEPTH][WIDTH];
    __shared__ float  s_win[WIDTH];
    __shared__ float  s_bin[WIDTH];
    __shared__ float  s_wout[WIDTH];

    const int t    = threadIdx.x;
    const int warp = t >> 5;
    const int lane = t & 31;
    const int g    = lane >> 2;
    const int q    = lane & 3;
    const int b    = blockIdx.z;
    const int sb   = blockIdx.y * SHALF;
    const int xi   = blockIdx.x * 4 + warp;

    // ---- stage this block's yu half + small weights ----
    for (int i = t; i < SHALF; i += TPB) {
        const float2* row = (const float2*)(yu + ((size_t)b * SS_DIM + sb + i) * (CC + DD));
        const float2 a0 = row[0], a1 = row[1], a2 = row[2], a3 = row[3], yv = row[4];
        float2* ur = (float2*)&s_u[i][0];
        ur[0] = a0; ur[1] = a1; ur[2] = a2; ur[3] = a3;
        s_y[i] = yv;
    }
    if (t < DEPTH * WIDTH) ((float*)s_bias)[t] = gbhid[t];
    if (t < WIDTH) {
        s_win[t]  = gWin[t];
        s_bin[t]  = gbin[t];
        s_wout[t] = gWout[t];
    }
    __syncthreads();

    const float bout = gbout[0];

    // ---- register-resident B fragments, 2-term fp16 split (exact weights) ----
    unsigned Bhi[DEPTH][2][2], Blo[DEPTH][2][2];
#pragma unroll
    for (int l = 0; l < DEPTH; ++l) {
        const float* Wl = gWhid + l * WIDTH * WIDTH;
#pragma unroll
        for (int nt = 0; nt < 2; ++nt) {
            const int n = g + 8 * nt;
            const float w00 = Wl[(2 * q) * WIDTH + n];
            const float w01 = Wl[(2 * q + 1) * WIDTH + n];
            const float w10 = Wl[(2 * q + 8) * WIDTH + n];
            const float w11 = Wl[(2 * q + 9) * WIDTH + n];
            split_pack_f16(w00, w01, Bhi[l][nt][0], Blo[l][nt][0]);
            split_pack_f16(w10, w11, Bhi[l][nt][1], Blo[l][nt][1]);
        }
    }

    const float2 xv = *(const float2*)(xin + ((size_t)b * XX + xi) * DD);

    float acc0 = 0.0f, acc1 = 0.0f;

#pragma unroll 1
    for (int ch = 0; ch < NCHUNK; ++ch) {
        const int s0 = ch * 32;

        const float2 yv = s_y[s0 + lane];
        const float dx0 = xv.x - yv.x;
        const float dx1 = xv.y - yv.y;
        const float r = fmaf(dx1, dx1, dx0 * dx0);
        const float r0 = __shfl_sync(0xffffffffu, r, g);
        const float r1 = __shfl_sync(0xffffffffu, r, g + 8);
        const float r2 = __shfl_sync(0xffffffffu, r, g + 16);
        const float r3 = __shfl_sync(0xffffffffu, r, g + 24);

        const float2 wA  = ((const float2*)s_win)[q];
        const float2 wB  = ((const float2*)(s_win + 8))[q];
        const float2 biA = ((const float2*)s_bin)[q];
        const float2 biB = ((const float2*)(s_bin + 8))[q];

        float hD[2][2][4];
#pragma unroll
        for (int nt = 0; nt < 2; ++nt) {
            const float2 wv = nt ? wB : wA;
            const float2 bv = nt ? biB : biA;
            hD[0][nt][0] = fmaf(r0, wv.x, bv.x);
            hD[0][nt][1] = fmaf(r0, wv.y, bv.y);
            hD[0][nt][2] = fmaf(r1, wv.x, bv.x);
            hD[0][nt][3] = fmaf(r1, wv.y, bv.y);
            hD[1][nt][0] = fmaf(r2, wv.x, bv.x);
            hD[1][nt][1] = fmaf(r2, wv.y, bv.y);
            hD[1][nt][2] = fmaf(r3, wv.x, bv.x);
            hD[1][nt][3] = fmaf(r3, wv.y, bv.y);
        }

#pragma unroll
        for (int l = 0; l < DEPTH; ++l) {
            const float2 bhA = ((const float2*)&s_bias[l][0])[q];
            const float2 bhB = ((const float2*)&s_bias[l][8])[q];
#pragma unroll
            for (int mt = 0; mt < 2; ++mt) {
                // single-fp16 A fragment: 4 CVTs, no residual
                unsigned a[4];
                a[0] = pack_f16x2(hD[mt][0][0], hD[mt][0][1]);
                a[1] = pack_f16x2(hD[mt][0][2], hD[mt][0][3]);
                a[2] = pack_f16x2(hD[mt][1][0], hD[mt][1][1]);
                a[3] = pack_f16x2(hD[mt][1][2], hD[mt][1][3]);
#pragma unroll
                for (int nt = 0; nt < 2; ++nt) {
                    float z[4];
                    mma_f16_init(z, a, Bhi[l][nt][0], Bhi[l][nt][1],
                                 nt ? bhB.x : bhA.x, nt ? bhB.y : bhA.y);
                    mma_f16(z, a, Blo[l][nt][0], Blo[l][nt][1]);
#pragma unroll
                    for (int c = 0; c < 4; ++c)
                        hD[mt][nt][c] += fast_tanh(z[c]);
                }
            }
        }

        const float2 woA = ((const float2*)s_wout)[q];
        const float2 woB = ((const float2*)(s_wout + 8))[q];
        float k[4];
#pragma unroll
        for (int mt = 0; mt < 2; ++mt) {
            float pg  = fmaf(hD[mt][0][0], woA.x,
                        fmaf(hD[mt][0][1], woA.y,
                        fmaf(hD[mt][1][0], woB.x, hD[mt][1][1] * woB.y)));
            float pg8 = fmaf(hD[mt][0][2], woA.x,
                        fmaf(hD[mt][0][3], woA.y,
                        fmaf(hD[mt][1][2], woB.x, hD[mt][1][3] * woB.y)));
            pg  += __shfl_xor_sync(0xffffffffu, pg, 1);
            pg  += __shfl_xor_sync(0xffffffffu, pg, 2);
            pg8 += __shfl_xor_sync(0xffffffffu, pg8, 1);
            pg8 += __shfl_xor_sync(0xffffffffu, pg8, 2);
            k[2 * mt]     = pg + bout;
            k[2 * mt + 1] = pg8 + bout;
        }

        const int srow[4] = {s0 + g, s0 + g + 8, s0 + 16 + g, s0 + 24 + g};
#pragma unroll
        for (int i = 0; i < 4; ++i) {
            const float2 uv = *(const float2*)&s_u[srow[i]][2 * q];
            acc0 = fmaf(k[i], uv.x, acc0);
            acc1 = fmaf(k[i], uv.y, acc1);
        }
    }

#pragma unroll
    for (int off = 4; off < 32; off <<= 1) {
        acc0 += __shfl_xor_sync(0xffffffffu, acc0, off);
        acc1 += __shfl_xor_sync(0xffffffffu, acc1, off);
    }
    if (lane < 4) {
        const float invS = 1.0f / (float)SS_DIM;
        float* op = out + ((size_t)b * XX + xi) * CC + 2 * lane;
        atomicAdd(op,     acc0 * invS);
        atomicAdd(op + 1, acc1 * invS);
    }
}

extern "C" void kernel_launch(void* const* d_in, const int* in_sizes, int n_in,
                              void* d_out, int out_size) {
    const float* yu    = (const float*)d_in[0]; // (4,1024,10)
    const float* x     = (const float*)d_in[1]; // (4,1024,2)
    const float* W_in  = (const float*)d_in[2]; // (1,16)
    const float* b_in  = (const float*)d_in[3]; // (16,)
    const float* W_hid = (const float*)d_in[4]; // (4,16,16)
    const float* b_hid = (const float*)d_in[5]; // (4,16)
    const float* W_out = (const float*)d_in[6]; // (16,1)
    const float* b_out = (const float*)d_in[7]; // (1,)

    (void)in_sizes; (void)n_in;

    cudaMemsetAsync(d_out, 0, (size_t)out_size * sizeof(float), 0);

    dim3 grid(XX / 4, SS_DIM / SHALF, BB);   // 256 x 2 x 4 = 2048 blocks (finer waves)
    ccl_kernel<<<grid, TPB, 0, 0>>>(yu, x, W_in, b_in, W_hid, b_hid, W_out, b_out,
                                    (float*)d_out);
}

// round 15
// speedup vs baseline: 1.7087x; 1.0545x over previous
#include <cuda_runtime.h>
#include <cuda_fp16.h>

#define BB 4
#define SS_DIM 1024
#define XX 1024
#define CC 8
#define DD 2
#define WIDTH 16
#define DEPTH 4
#define TPB 128
#define SHALF 512
#define NCHUNK (SHALF / 32)

__device__ __forceinline__ float fast_tanh(float x) {
    float y; asm("tanh.approx.f32 %0, %1;" : "=f"(y) : "f"(x)); return y;
}
// pack two f32 -> f16x2; e0 lands in LOWER half
__device__ __forceinline__ unsigned pack_f16x2(float e0, float e1) {
    unsigned d; asm("cvt.rn.f16x2.f32 %0, %1, %2;" : "=r"(d) : "f"(e1), "f"(e0)); return d;
}
__device__ __forceinline__ void mma_f16_init(float* d, const unsigned* a,
                                             unsigned b0, unsigned b1,
                                             float c0, float c1) {
    asm("mma.sync.aligned.m16n8k16.row.col.f32.f16.f16.f32 "
        "{%0,%1,%2,%3}, {%4,%5,%6,%7}, {%8,%9}, {%10,%11,%10,%11};"
        : "=f"(d[0]), "=f"(d[1]), "=f"(d[2]), "=f"(d[3])
        : "r"(a[0]), "r"(a[1]), "r"(a[2]), "r"(a[3]), "r"(b0), "r"(b1),
          "f"(c0), "f"(c1));
}

__global__ __launch_bounds__(TPB, 6)
void ccl_kernel(const float* __restrict__ yu,
                const float* __restrict__ xin,
                const float* __restrict__ gWin,
                const float* __restrict__ gbin,
                const float* __restrict__ gWhid,
                const float* __restrict__ gbhid,
                const float* __restrict__ gWout,
                const float* __restrict__ gbout,
                float* __restrict__ out) {
    __shared__ float  s_u[SHALF][CC];      // 16KB (this block's s-half)
    __shared__ float2 s_y[SHALF];          // 4KB
    __shared__ float  s_bias[DEPTH][WIDTH];
    __shared__ float  s_win[WIDTH];
    __shared__ float  s_bin[WIDTH];
    __shared__ float  s_wout[WIDTH];

    const int t    = threadIdx.x;
    const int warp = t >> 5;
    const int lane = t & 31;
    const int g    = lane >> 2;
    const int q    = lane & 3;
    const int b    = blockIdx.z;
    const int sb   = blockIdx.y * SHALF;
    const int xi   = blockIdx.x * 4 + warp;

    // ---- stage this block's yu half + small weights ----
    for (int i = t; i < SHALF; i += TPB) {
        const float2* row = (const float2*)(yu + ((size_t)b * SS_DIM + sb + i) * (CC + DD));
        const float2 a0 = row[0], a1 = row[1], a2 = row[2], a3 = row[3], yv = row[4];
        float2* ur = (float2*)&s_u[i][0];
        ur[0] = a0; ur[1] = a1; ur[2] = a2; ur[3] = a3;
        s_y[i] = yv;
    }
    if (t < DEPTH * WIDTH) ((float*)s_bias)[t] = gbhid[t];
    if (t < WIDTH) {
        s_win[t]  = gWin[t];
        s_bin[t]  = gbin[t];
        s_wout[t] = gWout[t];
    }
    __syncthreads();

    const float bout = gbout[0];

    // ---- register-resident B fragments, single fp16 (error budget verified) ----
    unsigned Bf[DEPTH][2][2];
#pragma unroll
    for (int l = 0; l < DEPTH; ++l) {
        const float* Wl = gWhid + l * WIDTH * WIDTH;
#pragma unroll
        for (int nt = 0; nt < 2; ++nt) {
            const int n = g + 8 * nt;
            Bf[l][nt][0] = pack_f16x2(Wl[(2 * q) * WIDTH + n],
                                      Wl[(2 * q + 1) * WIDTH + n]);
            Bf[l][nt][1] = pack_f16x2(Wl[(2 * q + 8) * WIDTH + n],
                                      Wl[(2 * q + 9) * WIDTH + n]);
        }
    }

    const float2 xv = *(const float2*)(xin + ((size_t)b * XX + xi) * DD);

    float acc0 = 0.0f, acc1 = 0.0f;

#pragma unroll 1
    for (int ch = 0; ch < NCHUNK; ++ch) {
        const int s0 = ch * 32;

        const float2 yv = s_y[s0 + lane];
        const float dx0 = xv.x - yv.x;
        const float dx1 = xv.y - yv.y;
        const float r = fmaf(dx1, dx1, dx0 * dx0);
        const float r0 = __shfl_sync(0xffffffffu, r, g);
        const float r1 = __shfl_sync(0xffffffffu, r, g + 8);
        const float r2 = __shfl_sync(0xffffffffu, r, g + 16);
        const float r3 = __shfl_sync(0xffffffffu, r, g + 24);

        const float2 wA  = ((const float2*)s_win)[q];
        const float2 wB  = ((const float2*)(s_win + 8))[q];
        const float2 biA = ((const float2*)s_bin)[q];
        const float2 biB = ((const float2*)(s_bin + 8))[q];

        float hD[2][2][4];
#pragma unroll
        for (int nt = 0; nt < 2; ++nt) {
            const float2 wv = nt ? wB : wA;
            const float2 bv = nt ? biB : biA;
            hD[0][nt][0] = fmaf(r0, wv.x, bv.x);
            hD[0][nt][1] = fmaf(r0, wv.y, bv.y);
            hD[0][nt][2] = fmaf(r1, wv.x, bv.x);
            hD[0][nt][3] = fmaf(r1, wv.y, bv.y);
            hD[1][nt][0] = fmaf(r2, wv.x, bv.x);
            hD[1][nt][1] = fmaf(r2, wv.y, bv.y);
            hD[1][nt][2] = fmaf(r3, wv.x, bv.x);
            hD[1][nt][3] = fmaf(r3, wv.y, bv.y);
        }

#pragma unroll
        for (int l = 0; l < DEPTH; ++l) {
            const float2 bhA = ((const float2*)&s_bias[l][0])[q];
            const float2 bhB = ((const float2*)&s_bias[l][8])[q];
#pragma unroll
            for (int mt = 0; mt < 2; ++mt) {
                // single-fp16 A fragment: 4 CVTs
                unsigned a[4];
                a[0] = pack_f16x2(hD[mt][0][0], hD[mt][0][1]);
                a[1] = pack_f16x2(hD[mt][0][2], hD[mt][0][3]);
                a[2] = pack_f16x2(hD[mt][1][0], hD[mt][1][1]);
                a[3] = pack_f16x2(hD[mt][1][2], hD[mt][1][3]);
#pragma unroll
                for (int nt = 0; nt < 2; ++nt) {
                    float z[4];
                    mma_f16_init(z, a, Bf[l][nt][0], Bf[l][nt][1],
                                 nt ? bhB.x : bhA.x, nt ? bhB.y : bhA.y);
#pragma unroll
                    for (int c = 0; c < 4; ++c)
                        hD[mt][nt][c] += fast_tanh(z[c]);
                }
            }
        }

        const float2 woA = ((const float2*)s_wout)[q];
        const float2 woB = ((const float2*)(s_wout + 8))[q];
        float k[4];
#pragma unroll
        for (int mt = 0; mt < 2; ++mt) {
            float pg  = fmaf(hD[mt][0][0], woA.x,
                        fmaf(hD[mt][0][1], woA.y,
                        fmaf(hD[mt][1][0], woB.x, hD[mt][1][1] * woB.y)));
            float pg8 = fmaf(hD[mt][0][2], woA.x,
                        fmaf(hD[mt][0][3], woA.y,
                        fmaf(hD[mt][1][2], woB.x, hD[mt][1][3] * woB.y)));
            pg  += __shfl_xor_sync(0xffffffffu, pg, 1);
            pg  += __shfl_xor_sync(0xffffffffu, pg, 2);
            pg8 += __shfl_xor_sync(0xffffffffu, pg8, 1);
            pg8 += __shfl_xor_sync(0xffffffffu, pg8, 2);
            k[2 * mt]     = pg + bout;
            k[2 * mt + 1] = pg8 + bout;
        }

        const int srow[4] = {s0 + g, s0 + g + 8, s0 + 16 + g, s0 + 24 + g};
#pragma unroll
        for (int i = 0; i < 4; ++i) {
            const float2 uv = *(const float2*)&s_u[srow[i]][2 * q];
            acc0 = fmaf(k[i], uv.x, acc0);
            acc1 = fmaf(k[i], uv.y, acc1);
        }
    }

#pragma unroll
    for (int off = 4; off < 32; off <<= 1) {
        acc0 += __shfl_xor_sync(0xffffffffu, acc0, off);
        acc1 += __shfl_xor_sync(0xffffffffu, acc1, off);
    }
    if (lane < 4) {
        const float invS = 1.0f / (float)SS_DIM;
        float* op = out + ((size_t)b * XX + xi) * CC + 2 * lane;
        atomicAdd(op,     acc0 * invS);
        atomicAdd(op + 1, acc1 * invS);
    }
}

extern "C" void kernel_launch(void* const* d_in, const int* in_sizes, int n_in,
                              void* d_out, int out_size) {
    const float* yu    = (const float*)d_in[0]; // (4,1024,10)
    const float* x     = (const float*)d_in[1]; // (4,1024,2)
    const float* W_in  = (const float*)d_in[2]; // (1,16)
    const float* b_in  = (const float*)d_in[3]; // (16,)
    const float* W_hid = (const float*)d_in[4]; // (4,16,16)
    const float* b_hid = (const float*)d_in[5]; // (4,16)
    const float* W_out = (const float*)d_in[6]; // (16,1)
    const float* b_out = (const float*)d_in[7]; // (1,)

    (void)in_sizes; (void)n_in;

    cudaMemsetAsync(d_out, 0, (size_t)out_size * sizeof(float), 0);

    dim3 grid(XX / 4, SS_DIM / SHALF, BB);   // 2048 blocks
    ccl_kernel<<<grid, TPB, 0, 0>>>(yu, x, W_in, b_in, W_hid, b_hid, W_out, b_out,
                                    (float*)d_out);
}